// round 14
// baseline (speedup 1.0000x reference)
#include <cuda_runtime.h>
#include <math.h>
#include <stdint.h>

#define BATCH 16
#define NP 6
#define NPTS 262144
#define BPB 64                          // blocks per batch element
#define NBLOCKS (BATCH*BPB)             // 1024
#define TPB 256
#define PTS_PER_BLOCK (NPTS/BPB)        // 4096
#define V4_PER_BLOCK (PTS_PER_BLOCK/4)  // 1024

typedef unsigned long long u64;

// ---- packed f32x2 helpers (sm_103a) ---------------------------------------
__device__ __forceinline__ u64 pk2(float lo, float hi) {
    u64 r; asm("mov.b64 %0,{%1,%2};" : "=l"(r) : "f"(lo), "f"(hi)); return r;
}
__device__ __forceinline__ void up2(u64 v, float& lo, float& hi) {
    asm("mov.b64 {%0,%1},%2;" : "=f"(lo), "=f"(hi) : "l"(v));
}
__device__ __forceinline__ u64 fma2_(u64 a, u64 b, u64 c) {
    u64 r; asm("fma.rn.f32x2 %0,%1,%2,%3;" : "=l"(r) : "l"(a), "l"(b), "l"(c)); return r;
}
__device__ __forceinline__ u64 mul2_(u64 a, u64 b) {
    u64 r; asm("mul.rn.f32x2 %0,%1,%2;" : "=l"(r) : "l"(a), "l"(b)); return r;
}
__device__ __forceinline__ float sqrt_approx(float x) {
    float s; asm("sqrt.approx.f32 %0,%1;" : "=f"(s) : "f"(x)); return s;
}

// Scratch (device globals — no allocation allowed)
__device__ float g_partial[NBLOCKS*NP];   // c-scaled per-block sums

// gamma^(P-1-p) for p=0..5, gamma=0.8
__device__ __constant__ float W_GAMMA[NP] =
    {0.32768f, 0.4096f, 0.512f, 0.64f, 0.8f, 1.0f};

// q_rel = conj(q_p) (x) q_t for (p,b).
__device__ __forceinline__ void qrel(const float* __restrict__ tq,
                                     const float* __restrict__ rq,
                                     int p, int b,
                                     float& w, float& x, float& y, float& z)
{
    float t0 = tq[b*4+0], t1 = tq[b*4+1], t2 = tq[b*4+2], t3 = tq[b*4+3];
    float rn = rsqrtf(t0*t0 + t1*t1 + t2*t2 + t3*t3);
    t0 *= rn; t1 *= rn; t2 *= rn; t3 *= rn;

    const float* q = rq + (size_t)(p*BATCH + b)*4;
    float a0 = q[0], a1 = q[1], a2 = q[2], a3 = q[3];
    rn = rsqrtf(a0*a0 + a1*a1 + a2*a2 + a3*a3);
    a0 *= rn; a1 = -a1*rn; a2 = -a2*rn; a3 = -a3*rn;   // conj, normalized

    w = a0*t0 - a1*t1 - a2*t2 - a3*t3;
    x = a0*t1 + a1*t0 + a2*t3 - a3*t2;
    y = a0*t2 - a1*t3 + a2*t0 + a3*t1;
    z = a0*t3 + a1*t2 - a2*t1 + a3*t0;
}

// ---------------------------------------------------------------------------
// Main kernel: axes live in SHARED (un-hoistable LDS per p) to free ~36 regs
// -> 5 CTAs/SM. f32x2 math, eps-biased r2 (no clamp).
// ---------------------------------------------------------------------------
__global__ __launch_bounds__(TPB)
void pc_kernel(const float* __restrict__ pc,
               const float* __restrict__ tq,
               const float* __restrict__ rq)
{
    int blk   = blockIdx.x;
    int b     = blk >> 6;               // / BPB
    int chunk = blk & (BPB - 1);

    __shared__ __align__(16) u64 s_axes[NP][4];   // [p] = {ux2, uy2, uz2, pad}
    __shared__ float s_c[NP];

    if (threadIdx.x < NP) {
        int p = threadIdx.x;
        float w, x, y, z;
        qrel(tq, rq, p, b, w, x, y, z);
        float vn = sqrtf(x*x + y*y + z*z);
        float ux, uy, uz;
        if (vn > 1e-20f) {
            float inv = 1.0f / vn;
            ux = x*inv; uy = y*inv; uz = z*inv;
            s_c[p] = 2.0f * vn;
        } else {
            ux = 1.0f; uy = 0.0f; uz = 0.0f; s_c[p] = 0.0f;
        }
        s_axes[p][0] = pk2(ux, ux);
        s_axes[p][1] = pk2(uy, uy);
        s_axes[p][2] = pk2(uz, uz);
        s_axes[p][3] = 0ull;
    }
    __syncthreads();

    uint32_t sa = (uint32_t)__cvta_generic_to_shared(&s_axes[0][0]);

    const size_t base = (size_t)b * 4 * NPTS + (size_t)chunk * PTS_PER_BLOCK;
    const ulonglong2* xr = (const ulonglong2*)(pc + base);            // pre-packed pairs
    const ulonglong2* yr = (const ulonglong2*)(pc + base + NPTS);
    const ulonglong2* zr = (const ulonglong2*)(pc + base + 2*NPTS);

    float accLo[NP], accHi[NP];
#pragma unroll
    for (int p = 0; p < NP; ++p) { accLo[p] = 0.0f; accHi[p] = 0.0f; }

    const u64 SGN  = 0x8000000080000000ULL;
    const u64 EPS2 = pk2(0.01f, 0.01f);   // rides the r2 fma chain for free

#pragma unroll 4
    for (int i = threadIdx.x; i < V4_PER_BLOCK; i += TPB) {
        ulonglong2 Xp = xr[i];           // .x = (x0,x1), .y = (x2,x3) packed
        ulonglong2 Yp = yr[i];
        ulonglong2 Zp = zr[i];

        u64 r2a = fma2_(Xp.x, Xp.x, fma2_(Yp.x, Yp.x, fma2_(Zp.x, Zp.x, EPS2)));
        u64 r2b = fma2_(Xp.y, Xp.y, fma2_(Yp.y, Yp.y, fma2_(Zp.y, Zp.y, EPS2)));

#pragma unroll
        for (int p = 0; p < NP; ++p) {
            u64 axx, axy, axz;
            // volatile: keep in shared; do NOT let ptxas re-materialize into regs
            asm volatile("ld.shared.v2.u64 {%0,%1},[%2];"
                         : "=l"(axx), "=l"(axy) : "r"(sa + p*32));
            asm volatile("ld.shared.b64 %0,[%1];"
                         : "=l"(axz) : "r"(sa + p*32 + 16));

            u64 d0 = fma2_(axx, Xp.x, fma2_(axy, Yp.x, mul2_(axz, Zp.x)));
            u64 t0 = fma2_(d0 ^ SGN, d0, r2a);
            u64 d1 = fma2_(axx, Xp.y, fma2_(axy, Yp.y, mul2_(axz, Zp.y)));
            u64 t1 = fma2_(d1 ^ SGN, d1, r2b);

            float a0, a1, b0, b1;
            up2(t0, a0, a1);
            up2(t1, b0, b1);
            accLo[p] += sqrt_approx(a0);
            accHi[p] += sqrt_approx(a1);
            accLo[p] += sqrt_approx(b0);
            accHi[p] += sqrt_approx(b1);
        }
    }

    // collapse halves, warp reduce, cross-warp via shared
    float acc[NP];
#pragma unroll
    for (int p = 0; p < NP; ++p) {
        acc[p] = accLo[p] + accHi[p];
#pragma unroll
        for (int off = 16; off > 0; off >>= 1)
            acc[p] += __shfl_down_sync(0xffffffffu, acc[p], off);
    }

    __shared__ float sh[TPB/32][NP];
    int warp = threadIdx.x >> 5, lane = threadIdx.x & 31;
    if (lane == 0) {
#pragma unroll
        for (int p = 0; p < NP; ++p) sh[warp][p] = acc[p];
    }
    __syncthreads();
    if (threadIdx.x < NP) {
        int p = threadIdx.x;
        float s = 0.0f;
#pragma unroll
        for (int wi = 0; wi < TPB/32; ++wi) s += sh[wi][p];
        g_partial[blk*NP + p] = s * s_c[p];          // apply c here
    }
}

// ---------------------------------------------------------------------------
// Final: 384 threads; 4-way split of the 64-partial sums (L2 resident).
// ---------------------------------------------------------------------------
__global__ void final_kernel(const float* __restrict__ tq,
                             const float* __restrict__ rq,
                             float* __restrict__ out)
{
    __shared__ float sh4[NP*BATCH][4];
    __shared__ float s_pcl[NP*BATCH];
    __shared__ float s_rot[NP*BATCH];
    int t = threadIdx.x;

    if (t < 4*NP*BATCH) {                 // 384 threads
        int g = t >> 2, k = t & 3;
        int p = g / BATCH, bb = g % BATCH;
        float s = 0.0f;
#pragma unroll
        for (int j = 0; j < BPB/4; ++j)   // 16 each
            s += __ldcg(&g_partial[((size_t)bb*BPB + k*(BPB/4) + j)*NP + p]);
        sh4[g][k] = s;
    }
    __syncthreads();

    if (t < NP*BATCH) {
        int p = t / BATCH, bb = t % BATCH;
        s_pcl[t] = (sh4[t][0] + sh4[t][1] + sh4[t][2] + sh4[t][3])
                   * (1.0f / (float)NPTS);
        float w, x, y, z;
        qrel(tq, rq, p, bb, w, x, y, z);
        s_rot[t] = 2.0f * atan2f(sqrtf(x*x + y*y + z*z), fabsf(w));
    }
    __syncthreads();

    if (t == 0) {
        float total = 0.0f, rl = 0.0f, pl = 0.0f;
#pragma unroll
        for (int p = 0; p < NP; ++p) {
            float pcl = 0.0f, rot = 0.0f;
#pragma unroll
            for (int bb = 0; bb < BATCH; ++bb) {
                pcl += s_pcl[p*BATCH + bb];
                rot += s_rot[p*BATCH + bb];
            }
            rot *= (1.0f / (float)BATCH);
            float pclB = pcl * (1.0f / (float)BATCH);
            float wgt = W_GAMMA[p];
            total += wgt * (0.5f * rot + 0.5f * pclB);
            rl    += wgt * rot;
            pl    += wgt * pclB;
        }
        out[0] = total; out[1] = rl; out[2] = pl;
    }
}

extern "C" void kernel_launch(void* const* d_in, const int* in_sizes, int n_in,
                              void* d_out, int out_size)
{
    (void)in_sizes; (void)n_in; (void)out_size;
    const float* pc = (const float*)d_in[0];   // point_clouds [B,4,N]
    // d_in[1] = target_transl (cancels analytically — unused)
    const float* tr = (const float*)d_in[2];   // target_rot [B,4]
    const float* rl = (const float*)d_in[3];   // rot_list [P,B,4]

    pc_kernel   <<<NBLOCKS, TPB>>>(pc, tr, rl);
    final_kernel<<<1, 384>>>(tr, rl, (float*)d_out);
}

// round 15
// speedup vs baseline: 1.1050x; 1.1050x over previous
#include <cuda_runtime.h>
#include <math.h>

#define BATCH 16
#define NP 6
#define NPTS 262144
#define BPB 64                          // blocks per batch element
#define NBLOCKS (BATCH*BPB)             // 1024
#define TPB 256
#define PTS_PER_BLOCK (NPTS/BPB)        // 4096
#define V4_PER_BLOCK (PTS_PER_BLOCK/4)  // 1024

typedef unsigned long long u64;

// ---- packed f32x2 helpers (sm_103a) ---------------------------------------
__device__ __forceinline__ u64 pk2(float lo, float hi) {
    u64 r; asm("mov.b64 %0,{%1,%2};" : "=l"(r) : "f"(lo), "f"(hi)); return r;
}
__device__ __forceinline__ void up2(u64 v, float& lo, float& hi) {
    asm("mov.b64 {%0,%1},%2;" : "=f"(lo), "=f"(hi) : "l"(v));
}
__device__ __forceinline__ u64 fma2_(u64 a, u64 b, u64 c) {
    u64 r; asm("fma.rn.f32x2 %0,%1,%2,%3;" : "=l"(r) : "l"(a), "l"(b), "l"(c)); return r;
}
__device__ __forceinline__ u64 mul2_(u64 a, u64 b) {
    u64 r; asm("mul.rn.f32x2 %0,%1,%2;" : "=l"(r) : "l"(a), "l"(b)); return r;
}
__device__ __forceinline__ float sqrt_approx(float x) {
    float s; asm("sqrt.approx.f32 %0,%1;" : "=f"(s) : "f"(x)); return s;
}

// Scratch (device globals — no allocation allowed)
__device__ float g_partial[NBLOCKS*NP];   // c-scaled per-block sums

// gamma^(P-1-p) for p=0..5, gamma=0.8
__device__ __constant__ float W_GAMMA[NP] =
    {0.32768f, 0.4096f, 0.512f, 0.64f, 0.8f, 1.0f};

// q_rel = conj(q_p) (x) q_t for (p,b).
__device__ __forceinline__ void qrel(const float* __restrict__ tq,
                                     const float* __restrict__ rq,
                                     int p, int b,
                                     float& w, float& x, float& y, float& z)
{
    float t0 = tq[b*4+0], t1 = tq[b*4+1], t2 = tq[b*4+2], t3 = tq[b*4+3];
    float rn = rsqrtf(t0*t0 + t1*t1 + t2*t2 + t3*t3);
    t0 *= rn; t1 *= rn; t2 *= rn; t3 *= rn;

    const float* q = rq + (size_t)(p*BATCH + b)*4;
    float a0 = q[0], a1 = q[1], a2 = q[2], a3 = q[3];
    rn = rsqrtf(a0*a0 + a1*a1 + a2*a2 + a3*a3);
    a0 *= rn; a1 = -a1*rn; a2 = -a2*rn; a3 = -a3*rn;   // conj, normalized

    w = a0*t0 - a1*t1 - a2*t2 - a3*t3;
    x = a0*t1 + a1*t0 + a2*t3 - a3*t2;
    y = a0*t2 - a1*t3 + a2*t0 + a3*t1;
    z = a0*t3 + a1*t2 - a2*t1 + a3*t0;
}

// ---------------------------------------------------------------------------
// Main kernel — R12 configuration (best stable measured): f32x2 + XOR,
// pre-packed loads, split scalar accumulators, fmax clamp.
// Signals dependent launch after publishing its partials.
// ---------------------------------------------------------------------------
__global__ __launch_bounds__(TPB)
void pc_kernel(const float* __restrict__ pc,
               const float* __restrict__ tq,
               const float* __restrict__ rq)
{
    int blk   = blockIdx.x;
    int b     = blk >> 6;               // / BPB
    int chunk = blk & (BPB - 1);

    __shared__ float s_ux[NP], s_uy[NP], s_uz[NP], s_c[NP];

    if (threadIdx.x < NP) {
        int p = threadIdx.x;
        float w, x, y, z;
        qrel(tq, rq, p, b, w, x, y, z);
        float vn = sqrtf(x*x + y*y + z*z);
        if (vn > 1e-20f) {
            float inv = 1.0f / vn;
            s_ux[p] = x*inv; s_uy[p] = y*inv; s_uz[p] = z*inv;
            s_c[p]  = 2.0f * vn;
        } else {
            s_ux[p] = 1.0f; s_uy[p] = 0.0f; s_uz[p] = 0.0f; s_c[p] = 0.0f;
        }
    }
    __syncthreads();

    u64 ux2[NP], uy2[NP], uz2[NP];
#pragma unroll
    for (int p = 0; p < NP; ++p) {
        ux2[p] = pk2(s_ux[p], s_ux[p]);
        uy2[p] = pk2(s_uy[p], s_uy[p]);
        uz2[p] = pk2(s_uz[p], s_uz[p]);
    }

    const size_t base = (size_t)b * 4 * NPTS + (size_t)chunk * PTS_PER_BLOCK;
    const ulonglong2* xr = (const ulonglong2*)(pc + base);            // pre-packed pairs
    const ulonglong2* yr = (const ulonglong2*)(pc + base + NPTS);
    const ulonglong2* zr = (const ulonglong2*)(pc + base + 2*NPTS);

    float accLo[NP], accHi[NP];
#pragma unroll
    for (int p = 0; p < NP; ++p) { accLo[p] = 0.0f; accHi[p] = 0.0f; }

    const u64 SGN = 0x8000000080000000ULL;

#pragma unroll 4
    for (int i = threadIdx.x; i < V4_PER_BLOCK; i += TPB) {
        ulonglong2 Xp = xr[i];           // .x = (x0,x1), .y = (x2,x3) packed
        ulonglong2 Yp = yr[i];
        ulonglong2 Zp = zr[i];
#pragma unroll
        for (int j = 0; j < 2; ++j) {
            u64 x = (j == 0) ? Xp.x : Xp.y;
            u64 y = (j == 0) ? Yp.x : Yp.y;
            u64 z = (j == 0) ? Zp.x : Zp.y;
            u64 r2 = fma2_(x, x, fma2_(y, y, mul2_(z, z)));
#pragma unroll
            for (int p = 0; p < NP; ++p) {
                u64 d  = fma2_(ux2[p], x, fma2_(uy2[p], y, mul2_(uz2[p], z)));
                u64 nd = d ^ SGN;                    // ALU pipe (idle)
                u64 t  = fma2_(nd, d, r2);           // r2 - d^2 (packed)
                float t0, t1; up2(t, t0, t1);
                accLo[p] += sqrt_approx(fmaxf(t0, 0.0f));
                accHi[p] += sqrt_approx(fmaxf(t1, 0.0f));
            }
        }
    }

    // collapse halves, warp reduce, cross-warp via shared
    float acc[NP];
#pragma unroll
    for (int p = 0; p < NP; ++p) {
        acc[p] = accLo[p] + accHi[p];
#pragma unroll
        for (int off = 16; off > 0; off >>= 1)
            acc[p] += __shfl_down_sync(0xffffffffu, acc[p], off);
    }

    __shared__ float sh[TPB/32][NP];
    int warp = threadIdx.x >> 5, lane = threadIdx.x & 31;
    if (lane == 0) {
#pragma unroll
        for (int p = 0; p < NP; ++p) sh[warp][p] = acc[p];
    }
    __syncthreads();
    if (threadIdx.x < NP) {
        int p = threadIdx.x;
        float s = 0.0f;
#pragma unroll
        for (int wi = 0; wi < TPB/32; ++wi) s += sh[wi][p];
        g_partial[blk*NP + p] = s * s_c[p];          // apply c here
    }
    __syncthreads();
    // allow the dependent (final) kernel to begin launching
    asm volatile("griddepcontrol.launch_dependents;");
}

// ---------------------------------------------------------------------------
// Final (PDL dependent): trig prologue overlaps pc_kernel's tail; waits on
// the grid dependency only before reading g_partial.
// ---------------------------------------------------------------------------
__global__ void final_kernel(const float* __restrict__ tq,
                             const float* __restrict__ rq,
                             float* __restrict__ out)
{
    __shared__ float sh4[NP*BATCH][4];
    __shared__ float s_pcl[NP*BATCH];
    __shared__ float s_rot[NP*BATCH];
    int t = threadIdx.x;

    // --- overlap window: no dependence on g_partial ---
    if (t < NP*BATCH) {
        int p = t / BATCH, bb = t % BATCH;
        float w, x, y, z;
        qrel(tq, rq, p, bb, w, x, y, z);
        s_rot[t] = 2.0f * atan2f(sqrtf(x*x + y*y + z*z), fabsf(w));
    }

    // --- wait for pc_kernel's partials ---
    asm volatile("griddepcontrol.wait;");

    if (t < 4*NP*BATCH) {                 // 384 threads
        int g = t >> 2, k = t & 3;
        int p = g / BATCH, bb = g % BATCH;
        float s = 0.0f;
#pragma unroll
        for (int j = 0; j < BPB/4; ++j)   // 16 each
            s += __ldcg(&g_partial[((size_t)bb*BPB + k*(BPB/4) + j)*NP + p]);
        sh4[g][k] = s;
    }
    __syncthreads();

    if (t < NP*BATCH) {
        s_pcl[t] = (sh4[t][0] + sh4[t][1] + sh4[t][2] + sh4[t][3])
                   * (1.0f / (float)NPTS);
    }
    __syncthreads();

    if (t == 0) {
        float total = 0.0f, rl = 0.0f, pl = 0.0f;
#pragma unroll
        for (int p = 0; p < NP; ++p) {
            float pcl = 0.0f, rot = 0.0f;
#pragma unroll
            for (int bb = 0; bb < BATCH; ++bb) {
                pcl += s_pcl[p*BATCH + bb];
                rot += s_rot[p*BATCH + bb];
            }
            rot *= (1.0f / (float)BATCH);
            float pclB = pcl * (1.0f / (float)BATCH);
            float wgt = W_GAMMA[p];
            total += wgt * (0.5f * rot + 0.5f * pclB);
            rl    += wgt * rot;
            pl    += wgt * pclB;
        }
        out[0] = total; out[1] = rl; out[2] = pl;
    }
}

extern "C" void kernel_launch(void* const* d_in, const int* in_sizes, int n_in,
                              void* d_out, int out_size)
{
    (void)in_sizes; (void)n_in; (void)out_size;
    const float* pc = (const float*)d_in[0];   // point_clouds [B,4,N]
    // d_in[1] = target_transl (cancels analytically — unused)
    const float* tr = (const float*)d_in[2];   // target_rot [B,4]
    const float* rl = (const float*)d_in[3];   // rot_list [P,B,4]

    pc_kernel<<<NBLOCKS, TPB>>>(pc, tr, rl);

    // dependent launch: overlaps with pc_kernel's tail via PDL
    cudaLaunchConfig_t cfg = {};
    cfg.gridDim  = dim3(1, 1, 1);
    cfg.blockDim = dim3(384, 1, 1);
    cudaLaunchAttribute attrs[1];
    attrs[0].id = cudaLaunchAttributeProgrammaticStreamSerialization;
    attrs[0].val.programmaticStreamSerializationAllowed = 1;
    cfg.attrs = attrs;
    cfg.numAttrs = 1;
    cudaLaunchKernelEx(&cfg, final_kernel, tr, rl, (float*)d_out);
}